// round 3
// baseline (speedup 1.0000x reference)
#include <cuda_runtime.h>
#include <cuda_bf16.h>

// Problem constants
#define BB 32
#define TT 2048
#define EE 1024
#define AA 1024
#define DD 1024
#define BT (BB * TT)   // 65536 rows

// Tiling for the big fused GEMM
#define TB 128   // rows (t) per block
#define KS 16    // k-step

// Scratch (no cudaMalloc allowed)
__device__ float g_decproj[BB * AA];           // W_dec @ dec + b_enc
__device__ float g_energy[BB * TT];            // pre-mask energies
__device__ float g_ctxpart[4][BB][EE];         // context partials over t-chunks

// ---------------------------------------------------------------------------
// Kernel A: dec_proj[b,a] = b_enc[a] + sum_d dec[b,d] * W_dec[d,a]
// grid (4, 32), 256 threads
// ---------------------------------------------------------------------------
__global__ __launch_bounds__(256) void decproj_kernel(
    const float* __restrict__ dec, const float* __restrict__ Wd,
    const float* __restrict__ benc)
{
    __shared__ float sdec[DD];
    const int b = blockIdx.y;
    for (int i = threadIdx.x; i < DD; i += 256) sdec[i] = dec[b * DD + i];
    __syncthreads();

    const int a = blockIdx.x * 256 + threadIdx.x;
    float acc = benc[a];
#pragma unroll 8
    for (int d = 0; d < DD; d++)
        acc = fmaf(sdec[d], Wd[(size_t)d * AA + a], acc);
    g_decproj[b * AA + a] = acc;
}

// ---------------------------------------------------------------------------
// Kernel B: energy[b,t] = sum_a v[a] * tanh( (enc @ W_enc)[b,t,a] + decproj[b,a] )
// Fused tiled SGEMM: each block owns a 128-row t-tile and iterates all 8
// 128-wide a-tiles sequentially (full k reduction per a-tile, then tanh+v-dot
// folded into a per-row shared accumulator). No atomics -> deterministic.
// grid (512), 256 threads, 8x8 micro-tile per thread.
// ---------------------------------------------------------------------------
__global__ __launch_bounds__(256, 2) void energy_kernel(
    const float* __restrict__ enc, const float* __restrict__ W,
    const float* __restrict__ v)
{
    __shared__ float sA[2][KS][TB];     // enc tile, [k][row]
    __shared__ float sB[2][KS][128];    // W tile,   [k][a]
    __shared__ float sE[TB][17];        // per-row energy partials (per tx), padded

    const int tid = threadIdx.x;
    const int tx = tid & 15;
    const int ty = tid >> 4;
    const int row0 = blockIdx.x * TB;
    const int b = row0 >> 11;           // row0 / 2048
    const float* __restrict__ dp = g_decproj + b * AA;

    for (int i = tid; i < TB * 17; i += 256) (&sE[0][0])[i] = 0.f;

    for (int at = 0; at < 8; at++) {
        const int a0 = at * 128;

        float acc[8][8];
#pragma unroll
        for (int i = 0; i < 8; i++)
#pragma unroll
            for (int j = 0; j < 8; j++) acc[i][j] = 0.f;

        float4 ra[2], rb[2];

        // --- prologue: load k-tile 0 into buffer 0 ---
#pragma unroll
        for (int p = 0; p < 2; p++) {
            int f4 = tid + p * 256;
            int arow = f4 >> 2, kq = f4 & 3;
            ra[p] = *reinterpret_cast<const float4*>(
                enc + (size_t)(row0 + arow) * EE + kq * 4);
            int bk = f4 >> 5, a4 = f4 & 31;
            rb[p] = *reinterpret_cast<const float4*>(
                W + (size_t)bk * AA + a0 + a4 * 4);
        }
#pragma unroll
        for (int p = 0; p < 2; p++) {
            int f4 = tid + p * 256;
            int arow = f4 >> 2, kq = f4 & 3;
            sA[0][kq * 4 + 0][arow] = ra[p].x;
            sA[0][kq * 4 + 1][arow] = ra[p].y;
            sA[0][kq * 4 + 2][arow] = ra[p].z;
            sA[0][kq * 4 + 3][arow] = ra[p].w;
            int bk = f4 >> 5, a4 = f4 & 31;
            *reinterpret_cast<float4*>(&sB[0][bk][a4 * 4]) = rb[p];
        }
        __syncthreads();

        for (int kt = 0; kt < EE / KS; kt++) {
            const int cur = kt & 1;
            // prefetch next k-tile (global -> regs)
            if (kt < EE / KS - 1) {
                const int kb = (kt + 1) * KS;
#pragma unroll
                for (int p = 0; p < 2; p++) {
                    int f4 = tid + p * 256;
                    int arow = f4 >> 2, kq = f4 & 3;
                    ra[p] = *reinterpret_cast<const float4*>(
                        enc + (size_t)(row0 + arow) * EE + kb + kq * 4);
                    int bk = f4 >> 5, a4 = f4 & 31;
                    rb[p] = *reinterpret_cast<const float4*>(
                        W + (size_t)(kb + bk) * AA + a0 + a4 * 4);
                }
            }
            // compute on current buffer
#pragma unroll
            for (int k = 0; k < KS; k++) {
                float4 a0v = *reinterpret_cast<const float4*>(&sA[cur][k][ty * 8]);
                float4 a1v = *reinterpret_cast<const float4*>(&sA[cur][k][ty * 8 + 4]);
                float4 b0v = *reinterpret_cast<const float4*>(&sB[cur][k][tx * 8]);
                float4 b1v = *reinterpret_cast<const float4*>(&sB[cur][k][tx * 8 + 4]);
                float rA[8] = {a0v.x, a0v.y, a0v.z, a0v.w, a1v.x, a1v.y, a1v.z, a1v.w};
                float rB[8] = {b0v.x, b0v.y, b0v.z, b0v.w, b1v.x, b1v.y, b1v.z, b1v.w};
#pragma unroll
                for (int i = 0; i < 8; i++)
#pragma unroll
                    for (int j = 0; j < 8; j++)
                        acc[i][j] = fmaf(rA[i], rB[j], acc[i][j]);
            }
            // stage prefetched regs -> next buffer
            if (kt < EE / KS - 1) {
                const int nxt = cur ^ 1;
#pragma unroll
                for (int p = 0; p < 2; p++) {
                    int f4 = tid + p * 256;
                    int arow = f4 >> 2, kq = f4 & 3;
                    sA[nxt][kq * 4 + 0][arow] = ra[p].x;
                    sA[nxt][kq * 4 + 1][arow] = ra[p].y;
                    sA[nxt][kq * 4 + 2][arow] = ra[p].z;
                    sA[nxt][kq * 4 + 3][arow] = ra[p].w;
                    int bk = f4 >> 5, a4 = f4 & 31;
                    *reinterpret_cast<float4*>(&sB[nxt][bk][a4 * 4]) = rb[p];
                }
            }
            __syncthreads();
        }

        // epilogue: tanh + v-dot, fold into per-row partials
        float dpv[8], vv[8];
#pragma unroll
        for (int j = 0; j < 8; j++) {
            int a = a0 + tx * 8 + j;
            dpv[j] = dp[a];
            vv[j]  = v[a];
        }
#pragma unroll
        for (int i = 0; i < 8; i++) {
            float es = 0.f;
#pragma unroll
            for (int j = 0; j < 8; j++)
                es = fmaf(vv[j], tanhf(acc[i][j] + dpv[j]), es);
            sE[ty * 8 + i][tx] += es;
        }
        __syncthreads();
    }

    if (tid < TB) {
        float s = 0.f;
#pragma unroll
        for (int x = 0; x < 16; x++) s += sE[tid][x];
        g_energy[row0 + tid] = s;
    }
}

// ---------------------------------------------------------------------------
// Kernel C: masked softmax over T per batch. energy * 0/1 mask (NOT -inf!).
// grid (32), 256 threads
// ---------------------------------------------------------------------------
__global__ __launch_bounds__(256) void softmax_kernel(
    const int* __restrict__ xlens, float* __restrict__ att)
{
    __shared__ float red[256];
    const int b = blockIdx.x;
    const int L = xlens[b];
    const float* __restrict__ e = g_energy + b * TT;

    float vals[8];
    float m = -1e30f;
#pragma unroll
    for (int i = 0; i < 8; i++) {
        int t = threadIdx.x + i * 256;
        float x = (t < L) ? e[t] : 0.f;   // masked positions contribute exp(0)
        vals[i] = x;
        m = fmaxf(m, x);
    }
    red[threadIdx.x] = m;
    __syncthreads();
    for (int s = 128; s > 0; s >>= 1) {
        if (threadIdx.x < s)
            red[threadIdx.x] = fmaxf(red[threadIdx.x], red[threadIdx.x + s]);
        __syncthreads();
    }
    m = red[0];
    __syncthreads();

    float sum = 0.f;
#pragma unroll
    for (int i = 0; i < 8; i++) {
        vals[i] = expf(vals[i] - m);
        sum += vals[i];
    }
    red[threadIdx.x] = sum;
    __syncthreads();
    for (int s = 128; s > 0; s >>= 1) {
        if (threadIdx.x < s)
            red[threadIdx.x] += red[threadIdx.x + s];
        __syncthreads();
    }
    const float inv = 1.0f / red[0];
#pragma unroll
    for (int i = 0; i < 8; i++) {
        int t = threadIdx.x + i * 256;
        att[b * TT + t] = vals[i] * inv;
    }
}

// ---------------------------------------------------------------------------
// Kernel D1: context partials over t-chunks (deterministic, no atomics)
// grid (4 e-chunks, 4 t-chunks, 32 b), 256 threads
// ---------------------------------------------------------------------------
__global__ __launch_bounds__(256) void context_part_kernel(
    const float* __restrict__ enc, const float* __restrict__ att)
{
    __shared__ float satt[512];
    const int ec = blockIdx.x;
    const int tc = blockIdx.y;
    const int b  = blockIdx.z;
    const int t0 = tc * 512;

    for (int i = threadIdx.x; i < 512; i += 256) satt[i] = att[b * TT + t0 + i];
    __syncthreads();

    const int e = ec * 256 + threadIdx.x;
    const float* __restrict__ p = enc + ((size_t)b * TT + t0) * EE + e;

    float a0 = 0.f, a1 = 0.f, a2 = 0.f, a3 = 0.f;
#pragma unroll 2
    for (int t = 0; t < 512; t += 4) {
        a0 = fmaf(p[(size_t)(t + 0) * EE], satt[t + 0], a0);
        a1 = fmaf(p[(size_t)(t + 1) * EE], satt[t + 1], a1);
        a2 = fmaf(p[(size_t)(t + 2) * EE], satt[t + 2], a2);
        a3 = fmaf(p[(size_t)(t + 3) * EE], satt[t + 3], a3);
    }
    g_ctxpart[tc][b][e] = (a0 + a1) + (a2 + a3);
}

// Kernel D2: reduce the 4 t-chunk partials -> context output
__global__ __launch_bounds__(256) void context_reduce_kernel(float* __restrict__ ctx)
{
    int i = blockIdx.x * 256 + threadIdx.x;   // 32*1024
    int b = i >> 10, e = i & 1023;
    ctx[i] = (g_ctxpart[0][b][e] + g_ctxpart[1][b][e]) +
             (g_ctxpart[2][b][e] + g_ctxpart[3][b][e]);
}

// ---------------------------------------------------------------------------
extern "C" void kernel_launch(void* const* d_in, const int* in_sizes, int n_in,
                              void* d_out, int out_size)
{
    const float* enc   = (const float*)d_in[0];
    const int*   xlens = (const int*)  d_in[1];
    const float* dec   = (const float*)d_in[2];
    // d_in[3] = att_weights_step (unused by reference)
    const float* Wenc  = (const float*)d_in[4];
    const float* benc  = (const float*)d_in[5];
    const float* Wdec  = (const float*)d_in[6];
    const float* v     = (const float*)d_in[7];

    float* out = (float*)d_out;
    float* ctx = out;                 // [B,1,E] = 32768 floats
    float* att = out + BB * EE;       // [B,T]   = 65536 floats

    decproj_kernel<<<dim3(4, BB), 256>>>(dec, Wdec, benc);
    energy_kernel<<<BT / TB, 256>>>(enc, Wenc, v);
    softmax_kernel<<<BB, 256>>>(xlens, att);
    context_part_kernel<<<dim3(4, 4, BB), 256>>>(enc, att);
    context_reduce_kernel<<<(BB * EE) / 256, 256>>>(ctx);
}

// round 4
// speedup vs baseline: 1.6363x; 1.6363x over previous
#include <cuda_runtime.h>
#include <cuda_bf16.h>
#include <cstdint>

// Problem constants
#define BB 32
#define TT 2048
#define EE 1024
#define AA 1024
#define DD 1024
#define BT (BB * TT)   // 65536 rows

// Scratch (no cudaMalloc allowed)
__device__ float g_decproj[BB * AA];           // W_dec @ dec + b_enc
__device__ float g_energy[BB * TT];            // pre-mask energies
__device__ float g_ctxpart[4][BB][EE];         // context partials over t-chunks

__device__ __forceinline__ uint32_t f2tf32(float x) {
    uint32_t r;
    asm("cvt.rna.tf32.f32 %0, %1;" : "=r"(r) : "f"(x));
    return r;
}

#define MMA_TF32(d, A0, A1, A2, A3, B0, B1)                                   \
    asm volatile(                                                             \
        "mma.sync.aligned.m16n8k8.row.col.f32.tf32.tf32.f32 "                 \
        "{%0,%1,%2,%3}, {%4,%5,%6,%7}, {%8,%9}, {%0,%1,%2,%3};"               \
        : "+f"(d[0]), "+f"(d[1]), "+f"(d[2]), "+f"(d[3])                      \
        : "r"(A0), "r"(A1), "r"(A2), "r"(A3), "r"(B0), "r"(B1))

// ---------------------------------------------------------------------------
// Kernel A: dec_proj[b,a] = b_enc[a] + sum_d dec[b,d] * W_dec[d,a]
// ---------------------------------------------------------------------------
__global__ __launch_bounds__(256) void decproj_kernel(
    const float* __restrict__ dec, const float* __restrict__ Wd,
    const float* __restrict__ benc)
{
    __shared__ float sdec[DD];
    const int b = blockIdx.y;
    for (int i = threadIdx.x; i < DD; i += 256) sdec[i] = dec[b * DD + i];
    __syncthreads();

    const int a = blockIdx.x * 256 + threadIdx.x;
    float acc = benc[a];
#pragma unroll 8
    for (int d = 0; d < DD; d++)
        acc = fmaf(sdec[d], Wd[(size_t)d * AA + a], acc);
    g_decproj[b * AA + a] = acc;
}

// ---------------------------------------------------------------------------
// Kernel B (tensor-core): energy[b,t] = sum_a v[a]*tanh(encproj[t,a]+decproj[b,a])
// mma.sync m16n8k8 tf32. Block: 128 t-rows, loops 8 a-tiles of 128, K-tile 16,
// double-buffered. 8 warps in 2x4 layout, 64x32 per warp.
// k-permutation: within each k8 step, thread-group c owns k = {2c, 2c+1}
// (applied identically to A and B fragments) -> vectorized conflict-free LDS.
// ---------------------------------------------------------------------------
__global__ __launch_bounds__(256) void energy_mma_kernel(
    const float* __restrict__ enc, const float* __restrict__ W,
    const float* __restrict__ v)
{
    __shared__ float sA[2][128][20];    // [t-row][k] (16 used, pad 20)
    __shared__ float sB[2][16][132];    // [k][a]     (128 used, pad 132)
    __shared__ float sE[128][5];        // per-row energy partials per wn

    const int tid  = threadIdx.x;
    const int lane = tid & 31, warp = tid >> 5;
    const int g    = lane >> 2, tig = lane & 3;
    const int wm   = warp & 1,  wn  = warp >> 1;
    const int row0 = blockIdx.x * 128;
    const int b    = row0 >> 11;

    for (int i = tid; i < 128 * 5; i += 256) (&sE[0][0])[i] = 0.f;

    // global->smem tiling indices (2 float4 per thread per tile per matrix)
    const int aRow = tid >> 2;     // + p*64
    const int aKq  = tid & 3;
    const int bKk  = tid >> 5;     // + p*8
    const int bA4  = tid & 31;

    for (int at = 0; at < 8; at++) {
        const int a0 = at * 128;

        float acc[4][4][4];
#pragma unroll
        for (int mi = 0; mi < 4; mi++)
#pragma unroll
            for (int ni = 0; ni < 4; ni++)
#pragma unroll
                for (int q = 0; q < 4; q++) acc[mi][ni][q] = 0.f;

        float4 ra[2], rb[2];

        // ---- prologue: k-tile 0 -> buffer 0 ----
#pragma unroll
        for (int p = 0; p < 2; p++) {
            ra[p] = *reinterpret_cast<const float4*>(
                enc + (size_t)(row0 + aRow + p * 64) * EE + aKq * 4);
            rb[p] = *reinterpret_cast<const float4*>(
                W + (size_t)(bKk + p * 8) * AA + a0 + bA4 * 4);
        }
#pragma unroll
        for (int p = 0; p < 2; p++) {
            float4 ta, tb;
            ta.x = __uint_as_float(f2tf32(ra[p].x));
            ta.y = __uint_as_float(f2tf32(ra[p].y));
            ta.z = __uint_as_float(f2tf32(ra[p].z));
            ta.w = __uint_as_float(f2tf32(ra[p].w));
            tb.x = __uint_as_float(f2tf32(rb[p].x));
            tb.y = __uint_as_float(f2tf32(rb[p].y));
            tb.z = __uint_as_float(f2tf32(rb[p].z));
            tb.w = __uint_as_float(f2tf32(rb[p].w));
            *reinterpret_cast<float4*>(&sA[0][aRow + p * 64][aKq * 4]) = ta;
            *reinterpret_cast<float4*>(&sB[0][bKk + p * 8][bA4 * 4])   = tb;
        }
        __syncthreads();

        for (int kt = 0; kt < 64; kt++) {
            const int cur = kt & 1;
            if (kt < 63) {
                const int kb = (kt + 1) * 16;
#pragma unroll
                for (int p = 0; p < 2; p++) {
                    ra[p] = *reinterpret_cast<const float4*>(
                        enc + (size_t)(row0 + aRow + p * 64) * EE + kb + aKq * 4);
                    rb[p] = *reinterpret_cast<const float4*>(
                        W + (size_t)(kb + bKk + p * 8) * AA + a0 + bA4 * 4);
                }
            }

            // ---- compute k16 (two k8 mma steps) ----
            float4 alo[4], ahi[4];
#pragma unroll
            for (int mi = 0; mi < 4; mi++) {
                const int r = wm * 64 + mi * 16 + g;
                alo[mi] = *reinterpret_cast<const float4*>(&sA[cur][r][4 * tig]);
                ahi[mi] = *reinterpret_cast<const float4*>(&sA[cur][r + 8][4 * tig]);
            }
#pragma unroll
            for (int s = 0; s < 2; s++) {
#pragma unroll
                for (int ni = 0; ni < 4; ni++) {
                    const int colB = wn * 32 + ni * 8 + g;
                    const uint32_t b0 = __float_as_uint(sB[cur][4 * tig + 2 * s][colB]);
                    const uint32_t b1 = __float_as_uint(sB[cur][4 * tig + 2 * s + 1][colB]);
#pragma unroll
                    for (int mi = 0; mi < 4; mi++) {
                        uint32_t A0, A1, A2, A3;
                        if (s == 0) {
                            A0 = __float_as_uint(alo[mi].x);
                            A1 = __float_as_uint(ahi[mi].x);
                            A2 = __float_as_uint(alo[mi].y);
                            A3 = __float_as_uint(ahi[mi].y);
                        } else {
                            A0 = __float_as_uint(alo[mi].z);
                            A1 = __float_as_uint(ahi[mi].z);
                            A2 = __float_as_uint(alo[mi].w);
                            A3 = __float_as_uint(ahi[mi].w);
                        }
                        MMA_TF32(acc[mi][ni], A0, A1, A2, A3, b0, b1);
                    }
                }
            }

            if (kt < 63) {
                const int nxt = cur ^ 1;
#pragma unroll
                for (int p = 0; p < 2; p++) {
                    float4 ta, tb;
                    ta.x = __uint_as_float(f2tf32(ra[p].x));
                    ta.y = __uint_as_float(f2tf32(ra[p].y));
                    ta.z = __uint_as_float(f2tf32(ra[p].z));
                    ta.w = __uint_as_float(f2tf32(ra[p].w));
                    tb.x = __uint_as_float(f2tf32(rb[p].x));
                    tb.y = __uint_as_float(f2tf32(rb[p].y));
                    tb.z = __uint_as_float(f2tf32(rb[p].z));
                    tb.w = __uint_as_float(f2tf32(rb[p].w));
                    *reinterpret_cast<float4*>(&sA[nxt][aRow + p * 64][aKq * 4]) = ta;
                    *reinterpret_cast<float4*>(&sB[nxt][bKk + p * 8][bA4 * 4])   = tb;
                }
            }
            __syncthreads();
        }

        // ---- epilogue: tanh + v-dot for this a-tile ----
        float dpv[8], vv[8];
#pragma unroll
        for (int ni = 0; ni < 4; ni++)
#pragma unroll
            for (int c = 0; c < 2; c++) {
                const int a = a0 + wn * 32 + ni * 8 + 2 * tig + c;
                dpv[ni * 2 + c] = g_decproj[b * AA + a];
                vv[ni * 2 + c]  = v[a];
            }
#pragma unroll
        for (int mi = 0; mi < 4; mi++) {
            float p0 = 0.f, p1 = 0.f;
#pragma unroll
            for (int ni = 0; ni < 4; ni++) {
                p0 = fmaf(vv[ni * 2 + 0], tanhf(acc[mi][ni][0] + dpv[ni * 2 + 0]), p0);
                p0 = fmaf(vv[ni * 2 + 1], tanhf(acc[mi][ni][1] + dpv[ni * 2 + 1]), p0);
                p1 = fmaf(vv[ni * 2 + 0], tanhf(acc[mi][ni][2] + dpv[ni * 2 + 0]), p1);
                p1 = fmaf(vv[ni * 2 + 1], tanhf(acc[mi][ni][3] + dpv[ni * 2 + 1]), p1);
            }
            p0 += __shfl_xor_sync(0xffffffffu, p0, 1);
            p0 += __shfl_xor_sync(0xffffffffu, p0, 2);
            p1 += __shfl_xor_sync(0xffffffffu, p1, 1);
            p1 += __shfl_xor_sync(0xffffffffu, p1, 2);
            if (tig == 0) {
                sE[wm * 64 + mi * 16 + g][wn]     += p0;
                sE[wm * 64 + mi * 16 + g + 8][wn] += p1;
            }
        }
        __syncthreads();
    }

    if (tid < 128) {
        g_energy[row0 + tid] = (sE[tid][0] + sE[tid][1]) + (sE[tid][2] + sE[tid][3]);
    }
}

// ---------------------------------------------------------------------------
// Kernel C: masked softmax over T per batch. energy * 0/1 mask (NOT -inf!).
// ---------------------------------------------------------------------------
__global__ __launch_bounds__(256) void softmax_kernel(
    const int* __restrict__ xlens, float* __restrict__ att)
{
    __shared__ float red[256];
    const int b = blockIdx.x;
    const int L = xlens[b];
    const float* __restrict__ e = g_energy + b * TT;

    float vals[8];
    float m = -1e30f;
#pragma unroll
    for (int i = 0; i < 8; i++) {
        int t = threadIdx.x + i * 256;
        float x = (t < L) ? e[t] : 0.f;   // masked positions contribute exp(0)
        vals[i] = x;
        m = fmaxf(m, x);
    }
    red[threadIdx.x] = m;
    __syncthreads();
    for (int s = 128; s > 0; s >>= 1) {
        if (threadIdx.x < s)
            red[threadIdx.x] = fmaxf(red[threadIdx.x], red[threadIdx.x + s]);
        __syncthreads();
    }
    m = red[0];
    __syncthreads();

    float sum = 0.f;
#pragma unroll
    for (int i = 0; i < 8; i++) {
        vals[i] = expf(vals[i] - m);
        sum += vals[i];
    }
    red[threadIdx.x] = sum;
    __syncthreads();
    for (int s = 128; s > 0; s >>= 1) {
        if (threadIdx.x < s)
            red[threadIdx.x] += red[threadIdx.x + s];
        __syncthreads();
    }
    const float inv = 1.0f / red[0];
#pragma unroll
    for (int i = 0; i < 8; i++) {
        int t = threadIdx.x + i * 256;
        att[b * TT + t] = vals[i] * inv;
    }
}

// ---------------------------------------------------------------------------
// Kernel D1: context partials over t-chunks (deterministic, no atomics)
// ---------------------------------------------------------------------------
__global__ __launch_bounds__(256) void context_part_kernel(
    const float* __restrict__ enc, const float* __restrict__ att)
{
    __shared__ float satt[512];
    const int ec = blockIdx.x;
    const int tc = blockIdx.y;
    const int b  = blockIdx.z;
    const int t0 = tc * 512;

    for (int i = threadIdx.x; i < 512; i += 256) satt[i] = att[b * TT + t0 + i];
    __syncthreads();

    const int e = ec * 256 + threadIdx.x;
    const float* __restrict__ p = enc + ((size_t)b * TT + t0) * EE + e;

    float a0 = 0.f, a1 = 0.f, a2 = 0.f, a3 = 0.f;
#pragma unroll 2
    for (int t = 0; t < 512; t += 4) {
        a0 = fmaf(p[(size_t)(t + 0) * EE], satt[t + 0], a0);
        a1 = fmaf(p[(size_t)(t + 1) * EE], satt[t + 1], a1);
        a2 = fmaf(p[(size_t)(t + 2) * EE], satt[t + 2], a2);
        a3 = fmaf(p[(size_t)(t + 3) * EE], satt[t + 3], a3);
    }
    g_ctxpart[tc][b][e] = (a0 + a1) + (a2 + a3);
}

// Kernel D2: reduce the 4 t-chunk partials -> context output
__global__ __launch_bounds__(256) void context_reduce_kernel(float* __restrict__ ctx)
{
    int i = blockIdx.x * 256 + threadIdx.x;   // 32*1024
    int b = i >> 10, e = i & 1023;
    ctx[i] = (g_ctxpart[0][b][e] + g_ctxpart[1][b][e]) +
             (g_ctxpart[2][b][e] + g_ctxpart[3][b][e]);
}

// ---------------------------------------------------------------------------
extern "C" void kernel_launch(void* const* d_in, const int* in_sizes, int n_in,
                              void* d_out, int out_size)
{
    const float* enc   = (const float*)d_in[0];
    const int*   xlens = (const int*)  d_in[1];
    const float* dec   = (const float*)d_in[2];
    // d_in[3] = att_weights_step (unused by reference)
    const float* Wenc  = (const float*)d_in[4];
    const float* benc  = (const float*)d_in[5];
    const float* Wdec  = (const float*)d_in[6];
    const float* v     = (const float*)d_in[7];

    float* out = (float*)d_out;
    float* ctx = out;                 // [B,1,E] = 32768 floats
    float* att = out + BB * EE;       // [B,T]   = 65536 floats

    decproj_kernel<<<dim3(4, BB), 256>>>(dec, Wdec, benc);
    energy_mma_kernel<<<BT / 128, 256>>>(enc, Wenc, v);
    softmax_kernel<<<BB, 256>>>(xlens, att);
    context_part_kernel<<<dim3(4, 4, BB), 256>>>(enc, att);
    context_reduce_kernel<<<(BB * EE) / 256, 256>>>(ctx);
}